// round 12
// baseline (speedup 1.0000x reference)
#include <cuda_runtime.h>

#define BATCH 16
#define H 256
#define W 256
#define HW (H*W)
#define NPLANE 12            // unique off-center taps (center weight == 1)
#define RAD 2
#define NITER 10
#define GB 8                 // batches per phase (L2 working set ~51.5 MB)

// padded weight plane: 2 cols left, 2 cols right, 2 rows bottom (zeros)
#define PW 260
#define PH 258
#define PLANE (PW*PH)

// mean-field tile: 512 threads, 1 px/thread -> 64x8 pixels
#define NT 512
#define TILEW 64
#define TH 8
#define SHW (TILEW + 2*RAD)   // 68
#define SHH (TH + 2*RAD)      // 12

// persistent grid: 512 blocks x 2 tiles each = 1024 tiles per phase
#define PBLKS 512

// build tile: 32x8 px
#define BTW 32
#define BHALOW (BTW + 2*RAD)  // 36
#define BHALOH (TH + 2*RAD)   // 12

// Scratch (no cudaMalloc): ~137 MB of __device__ globals.
__device__ float2 g_k[BATCH * NPLANE * PLANE];  // interleaved {kA,kB}, padded
__device__ float4 g_L[2][BATCH * HW];           // {logxA, log1mxA, logxB, log1mxB}
__device__ unsigned int g_cnt[BATCH * 8];

// grid barrier state (self-resetting; monotonic counter is graph-replay safe)
__device__ unsigned int g_arrive = 0;
__device__ volatile unsigned int g_epoch = 0;

// ---------------------------------------------------------------------------
__global__ __launch_bounds__(256) void zero_pad() {
    float2* p = g_k + (size_t)blockIdx.x * PLANE;
    const float2 z = make_float2(0.f, 0.f);
    for (int i = threadIdx.x; i < 2 * PW; i += 256) {
        int r = 256 + i / PW, c = i % PW;
        p[r * PW + c] = z;
    }
    for (int i = threadIdx.x; i < 256 * 4; i += 256) {
        int r = i / 4, cc = i % 4;
        int c = (cc < 2) ? cc : (256 + cc);
        p[r * PW + c] = z;
    }
    if (blockIdx.x == 0 && threadIdx.x < BATCH * 8)
        g_cnt[threadIdx.x] = 0u;
}

// ---------------------------------------------------------------------------
// Build 12 unique-tap weight plane pairs per batch; fused mean-field init.
// ---------------------------------------------------------------------------
__global__ __launch_bounds__(256) void build_kernels(
    const float* __restrict__ fm, const float* __restrict__ depth,
    const float* __restrict__ seg) {
    __shared__ float sf0[BHALOH][BHALOW];
    __shared__ float sf1[BHALOH][BHALOW];
    __shared__ float sf2[BHALOH][BHALOW];
    __shared__ float sd [BHALOH][BHALOW];

    int b   = blockIdx.z;
    int ty0 = blockIdx.y * TH;
    int tx0 = blockIdx.x * BTW;
    int tid = threadIdx.y * BTW + threadIdx.x;

    for (int i = tid; i < BHALOH * BHALOW; i += TH * BTW) {
        int hy = i / BHALOW, hx = i % BHALOW;
        int gy = ty0 + hy - RAD, gx = tx0 + hx - RAD;
        float f0 = 0.f, f1 = 0.f, f2 = 0.f, d = 0.f;
        if (gy >= 0 && gy < H && gx >= 0 && gx < W) {
            int idx = gy * W + gx;
            f0 = fm[(b * 3 + 0) * HW + idx] + 10.f;
            f1 = fm[(b * 3 + 1) * HW + idx] + 10.f;
            f2 = fm[(b * 3 + 2) * HW + idx] + 10.f;
            d  = depth[b * HW + idx];
        }
        sf0[hy][hx] = f0; sf1[hy][hx] = f1; sf2[hy][hx] = f2; sd[hy][hx] = d;
    }
    __syncthreads();

    int ly = threadIdx.y, lx = threadIdx.x;
    int gy = ty0 + ly, gx = tx0 + lx;

    float c0 = sf0[ly + RAD][lx + RAD];
    float c1 = sf1[ly + RAD][lx + RAD];
    float c2 = sf2[ly + RAD][lx + RAD];
    float cd = sd [ly + RAD][lx + RAD];

    float2* kout = g_k + (size_t)(b * NPLANE) * PLANE + gy * PW + (gx + 2);

    #pragma unroll
    for (int t = 0; t < NPLANE; t++) {
        int kh = t / 5, kw = t % 5;
        float d0 = sf0[ly + kh][lx + kw] - c0;
        float d1 = sf1[ly + kh][lx + kw] - c1;
        float d2 = sf2[ly + kh][lx + kw] - c2;
        float s  = d0 * d0 + d1 * d1 + d2 * d2;
        float k  = expf(-(s / 0.02f));
        float dd = sd[ly + kh][lx + kw] - cd;
        float ks = k * expf(-((dd * dd) / 0.02f));
        kout[(size_t)t * PLANE] = make_float2(k, ks);
    }

    {
        int idx = b * HW + gy * W + gx;
        float x = fminf(fmaxf(seg[idx], 0.1f), 0.9f);
        float l1 = logf(x), l0 = logf(1.0f - x);
        g_L[0][idx] = make_float4(l1, l0, l1, l0);
    }
}

// ---------------------------------------------------------------------------
// Grid-wide barrier: monotonic epoch counter, self-resetting arrive count.
// Safe because all PBLKS blocks are co-resident (512 <= 148 SMs * 4 blocks).
// ---------------------------------------------------------------------------
__device__ __forceinline__ void grid_barrier() {
    __syncthreads();
    if (threadIdx.x == 0) {
        __threadfence();
        unsigned int target = g_epoch + 1;     // read before arriving
        unsigned int prev = atomicAdd(&g_arrive, 1u);
        if (prev == PBLKS - 1) {
            g_arrive = 0;
            __threadfence();
            g_epoch = target;
        } else {
            while (g_epoch < target) __nanosleep(64);
        }
        __threadfence();
    }
    __syncthreads();
}

// ---------------------------------------------------------------------------
// One tile of one mean-field iteration (both chains, float4-packed).
// ---------------------------------------------------------------------------
__device__ __forceinline__ void do_tile(
    int b, int ty0, int tx0, int src, int last,
    const float* __restrict__ seg, const float* __restrict__ targets,
    const float* __restrict__ sam, float* __restrict__ out_mask,
    float4 (&sb)[SHH][SHW]) {
    int tid = threadIdx.x;

    const float4* __restrict__ Ls = g_L[src];
    float4* Ld = g_L[src ^ 1];

    if (ty0 >= RAD && ty0 + TH + RAD <= H && tx0 >= RAD && tx0 + TILEW + RAD <= W) {
        #pragma unroll
        for (int i = tid; i < SHH * SHW; i += NT) {
            int hy = i / SHW, hx = i % SHW;
            sb[hy][hx] = __ldcs(&Ls[b * HW + (ty0 + hy - RAD) * W + (tx0 + hx - RAD)]);
        }
    } else {
        #pragma unroll
        for (int i = tid; i < SHH * SHW; i += NT) {
            int hy = i / SHW, hx = i % SHW;
            int gy = ty0 + hy - RAD, gx = tx0 + hx - RAD;
            float4 v = make_float4(0.f, 0.f, 0.f, 0.f);
            if ((unsigned)gy < H && (unsigned)gx < W)
                v = __ldcs(&Ls[b * HW + gy * W + gx]);
            sb[hy][hx] = v;
        }
    }
    __syncthreads();

    int lx = tid & (TILEW - 1);
    int ly = tid >> 6;
    int gy = ty0 + ly, gx = tx0 + lx;

    const float2* __restrict__ kp =
        g_k + (size_t)(b * NPLANE) * PLANE + gy * PW + (gx + 2);

    float S1A = 0.f, S0A = 0.f, S1B = 0.f, S0B = 0.f;

    #pragma unroll
    for (int t = 0; t < NPLANE; t++) {
        const int kh = t / 5, kw = t % 5;
        const int moff = (2 - kh) * PW + (2 - kw);
        float2 wf = __ldg(kp + (size_t)t * PLANE);
        float2 wm = __ldg(kp + (size_t)t * PLANE + moff);

        float4 f = sb[ly + kh][lx + kw];
        float4 m = sb[ly + 4 - kh][lx + 4 - kw];

        S1A += wf.x * f.x + wm.x * m.x;
        S0A += wf.x * f.y + wm.x * m.y;
        S1B += wf.y * f.z + wm.y * m.z;
        S0B += wf.y * f.w + wm.y * m.w;
    }
    {
        float4 c = sb[ly + 2][lx + 2];
        S1A += c.x; S0A += c.y; S1B += c.z; S0B += c.w;
    }

    int idx = b * HW + gy * W + gx;

    float a1, a0;
    a1 = expf(S1A); a0 = expf(S0A);
    float xA = fminf(fmaxf(a1 / (1e-6f + (a0 + a1)), 0.1f), 0.9f);
    a1 = expf(S1B); a0 = expf(S0B);
    float xB = fminf(fmaxf(a1 / (1e-6f + (a0 + a1)), 0.1f), 0.9f);

    if (!last) {
        __stcs(&Ld[idx], make_float4(logf(xA), logf(1.0f - xA),
                                     logf(xB), logf(1.0f - xB)));
    } else {
        bool t0 = (targets[idx] != 0.f);
        bool p0 = (seg[idx]  > 0.5f);
        bool p1 = (xA > 0.5f);
        bool p2 = (xB > 0.5f);
        bool p3 = (sam[idx] != 0.f);

        __stcs(&out_mask[idx], p1 ? 1.f : 0.f);

        __shared__ unsigned int c[8];
        if (tid < 8) c[tid] = 0u;
        __syncthreads();

        bool pr[4] = {p0, p1, p2, p3};
        int lane = tid & 31;
        #pragma unroll
        for (int m = 0; m < 4; m++) {
            unsigned bi = __ballot_sync(0xFFFFFFFFu, t0 && pr[m]);
            unsigned bu = __ballot_sync(0xFFFFFFFFu, t0 || pr[m]);
            if (lane == 0) {
                atomicAdd(&c[2 * m + 0], (unsigned)__popc(bi));
                atomicAdd(&c[2 * m + 1], (unsigned)__popc(bu));
            }
        }
        __syncthreads();
        if (tid < 8)
            atomicAdd(&g_cnt[b * 8 + tid], c[tid]);
    }
    __syncthreads();   // protect smem before next tile reuses it
}

// ---------------------------------------------------------------------------
// Persistent mean-field kernel: 2 phases x 10 iterations, grid barrier
// between iterations. Each block owns tiles 2*bid and 2*bid+1 of each phase
// (fixed mapping -> weight region stays L1-resident across iterations).
// ---------------------------------------------------------------------------
__global__ __launch_bounds__(NT, 4) void mf_persist(
    const float* __restrict__ seg, const float* __restrict__ targets,
    const float* __restrict__ sam, float* __restrict__ out_mask) {
    __shared__ float4 sb[SHH][SHW];

    #pragma unroll 1
    for (int step = 0; step < 2 * NITER; step++) {
        int g    = (step >= NITER) ? 1 : 0;
        int it   = step - g * NITER;
        int src  = it & 1;
        int last = (it == NITER - 1);

        #pragma unroll 1
        for (int s = 0; s < 2; s++) {
            int tile = blockIdx.x * 2 + s;          // 0..1023
            int tx0  = (tile & 3) * TILEW;
            int ty0  = ((tile >> 2) & 31) * TH;
            int b    = g * GB + (tile >> 7);
            do_tile(b, ty0, tx0, src, last, seg, targets, sam, out_mask, sb);
        }
        if (step != 2 * NITER - 1)
            grid_barrier();
    }
}

__global__ void iou_kernel(float* __restrict__ out_ious) {
    int m = threadIdx.x;
    if (m < 4) {
        float s = 0.f;
        for (int b = 0; b < BATCH; b++) {
            float inter = (float)g_cnt[b * 8 + 2 * m + 0];
            float uni   = (float)g_cnt[b * 8 + 2 * m + 1];
            s += inter / (uni + 1e-6f);
        }
        out_ious[m] = s * (1.0f / (float)BATCH);
    }
}

// ---------------------------------------------------------------------------
extern "C" void kernel_launch(void* const* d_in, const int* in_sizes, int n_in,
                              void* d_out, int out_size) {
    const float* fm      = (const float*)d_in[0];  // (16,3,256,256)
    const float* seg     = (const float*)d_in[1];  // (16,256,256)
    const float* depth   = (const float*)d_in[2];
    const float* targets = (const float*)d_in[3];
    const float* sam     = (const float*)d_in[4];
    float* out = (float*)d_out;

    zero_pad<<<BATCH * NPLANE, 256>>>();
    build_kernels<<<dim3(W / BTW, H / TH, BATCH), dim3(BTW, TH)>>>(fm, depth, seg);

    // One persistent launch runs all 2 phases x 10 iterations with grid
    // barriers (512 blocks <= guaranteed-resident 592 at 4 blocks/SM).
    mf_persist<<<PBLKS, NT>>>(seg, targets, sam, out);

    iou_kernel<<<1, 32>>>(out + (out_size - 4));
}

// round 13
// speedup vs baseline: 1.1350x; 1.1350x over previous
#include <cuda_runtime.h>

#define BATCH 16
#define H 256
#define W 256
#define HW (H*W)
#define NPLANE 12            // unique off-center taps (center weight == 1)
#define RAD 2
#define NITER 10
#define GB 8                 // batches per phase (L2 working set ~51.5 MB)

// padded weight plane: 2 cols left, 2 cols right, 2 rows bottom (zeros)
#define PW 260
#define PH 258
#define PLANE (PW*PH)

// mf_iter tile: 512 threads, 1 px/thread -> 64x8 pixels
#define NT 512
#define TILEW 64
#define TH 8
#define SHW (TILEW + 2*RAD)   // 68
#define SHH (TH + 2*RAD)      // 12

// build tile: 32x8 px
#define BTW 32
#define BHALOW (BTW + 2*RAD)  // 36
#define BHALOH (TH + 2*RAD)   // 12

// Scratch (no cudaMalloc): ~137 MB of __device__ globals.
__device__ float2 g_k[BATCH * NPLANE * PLANE];  // interleaved {kA,kB}, padded
__device__ float4 g_L[2][BATCH * HW];           // {logxA, log1mxA, logxB, log1mxB}
__device__ unsigned int g_cnt[BATCH * 8];

// ---------------------------------------------------------------------------
// Zero the padding borders of every weight plane; zero IoU counters.
// ---------------------------------------------------------------------------
__global__ __launch_bounds__(256) void zero_pad() {
    float2* p = g_k + (size_t)blockIdx.x * PLANE;
    const float2 z = make_float2(0.f, 0.f);
    for (int i = threadIdx.x; i < 2 * PW; i += 256) {
        int r = 256 + i / PW, c = i % PW;
        p[r * PW + c] = z;
    }
    for (int i = threadIdx.x; i < 256 * 4; i += 256) {
        int r = i / 4, cc = i % 4;
        int c = (cc < 2) ? cc : (256 + cc);
        p[r * PW + c] = z;
    }
    if (blockIdx.x == 0 && threadIdx.x < BATCH * 8)
        g_cnt[threadIdx.x] = 0u;
}

// ---------------------------------------------------------------------------
// Build 12 unique-tap weight plane pairs per batch (mirror taps come from
// shifted reads of these planes; center tap weight is exactly 1).
// Fused: also initializes L0 = {log x0, log(1-x0)} x2 from seg.
// ---------------------------------------------------------------------------
__global__ __launch_bounds__(256) void build_kernels(
    const float* __restrict__ fm, const float* __restrict__ depth,
    const float* __restrict__ seg) {
    __shared__ float sf0[BHALOH][BHALOW];
    __shared__ float sf1[BHALOH][BHALOW];
    __shared__ float sf2[BHALOH][BHALOW];
    __shared__ float sd [BHALOH][BHALOW];

    int b   = blockIdx.z;
    int ty0 = blockIdx.y * TH;
    int tx0 = blockIdx.x * BTW;
    int tid = threadIdx.y * BTW + threadIdx.x;

    for (int i = tid; i < BHALOH * BHALOW; i += TH * BTW) {
        int hy = i / BHALOW, hx = i % BHALOW;
        int gy = ty0 + hy - RAD, gx = tx0 + hx - RAD;
        float f0 = 0.f, f1 = 0.f, f2 = 0.f, d = 0.f;
        if (gy >= 0 && gy < H && gx >= 0 && gx < W) {
            int idx = gy * W + gx;
            f0 = fm[(b * 3 + 0) * HW + idx] + 10.f;
            f1 = fm[(b * 3 + 1) * HW + idx] + 10.f;
            f2 = fm[(b * 3 + 2) * HW + idx] + 10.f;
            d  = depth[b * HW + idx];
        }
        sf0[hy][hx] = f0; sf1[hy][hx] = f1; sf2[hy][hx] = f2; sd[hy][hx] = d;
    }
    __syncthreads();

    int ly = threadIdx.y, lx = threadIdx.x;
    int gy = ty0 + ly, gx = tx0 + lx;

    float c0 = sf0[ly + RAD][lx + RAD];
    float c1 = sf1[ly + RAD][lx + RAD];
    float c2 = sf2[ly + RAD][lx + RAD];
    float cd = sd [ly + RAD][lx + RAD];

    float2* kout = g_k + (size_t)(b * NPLANE) * PLANE + gy * PW + (gx + 2);

    #pragma unroll
    for (int t = 0; t < NPLANE; t++) {
        int kh = t / 5, kw = t % 5;
        float d0 = sf0[ly + kh][lx + kw] - c0;
        float d1 = sf1[ly + kh][lx + kw] - c1;
        float d2 = sf2[ly + kh][lx + kw] - c2;
        float s  = d0 * d0 + d1 * d1 + d2 * d2;
        float k  = expf(-(s / 0.02f));
        float dd = sd[ly + kh][lx + kw] - cd;
        float ks = k * expf(-((dd * dd) / 0.02f));
        kout[(size_t)t * PLANE] = make_float2(k, ks);
    }

    // fused mean-field init: x0 = clip(seg, 0.1, 0.9); store log pair x2
    {
        int idx = b * HW + gy * W + gx;
        float x = fminf(fmaxf(seg[idx], 0.1f), 0.9f);
        float l1 = logf(x), l0 = logf(1.0f - x);
        g_L[0][idx] = make_float4(l1, l0, l1, l0);
    }
}

// ---------------------------------------------------------------------------
// One mean-field iteration, both chains packed in float4, 1 px/thread,
// 512-thread blocks, 4 blocks/SM (32-reg cap -> ~100% theoretical occ):
//   S(p) = L(p) + sum_t [ w_t(p) * L(p+o_t) + w_t(p-o_t) * L(p-o_t) ]
// GB=8 phase per launch (weights L2-resident across the phase's 10 iters).
// Last iteration fuses mask write + IoU counting. (Exact round-8 body.)
// ---------------------------------------------------------------------------
__global__ __launch_bounds__(NT, 4) void mf_iter(
    int src, int last, int b0,
    const float* __restrict__ seg, const float* __restrict__ targets,
    const float* __restrict__ sam, float* __restrict__ out_mask) {
    __shared__ float4 sb[SHH][SHW];   // {logxA, log1mxA, logxB, log1mxB}

    int b   = b0 + blockIdx.z;
    int ty0 = blockIdx.y * TH;
    int tx0 = blockIdx.x * TILEW;
    int tid = threadIdx.x;

    const float4* __restrict__ Ls = g_L[src];
    float4* Ld = g_L[src ^ 1];

    #pragma unroll
    for (int i = tid; i < SHH * SHW; i += NT) {
        int hy = i / SHW, hx = i % SHW;
        int gy = ty0 + hy - RAD, gx = tx0 + hx - RAD;
        float4 v = make_float4(0.f, 0.f, 0.f, 0.f);
        if ((unsigned)gy < H && (unsigned)gx < W)
            v = __ldcs(&Ls[b * HW + gy * W + gx]);
        sb[hy][hx] = v;
    }
    __syncthreads();

    int lx = tid & (TILEW - 1);       // 0..63, lanes consecutive in x
    int ly = tid >> 6;                // 0..7
    int gy = ty0 + ly, gx = tx0 + lx;

    const float2* __restrict__ kp =
        g_k + (size_t)(b * NPLANE) * PLANE + gy * PW + (gx + 2);

    float S1A = 0.f, S0A = 0.f, S1B = 0.f, S0B = 0.f;

    #pragma unroll
    for (int t = 0; t < NPLANE; t++) {
        const int kh = t / 5, kw = t % 5;
        const int moff = (2 - kh) * PW + (2 - kw);   // mirror weight offset
        float2 wf = __ldg(kp + (size_t)t * PLANE);
        float2 wm = __ldg(kp + (size_t)t * PLANE + moff);

        float4 f = sb[ly + kh][lx + kw];
        float4 m = sb[ly + 4 - kh][lx + 4 - kw];

        S1A += wf.x * f.x + wm.x * m.x;
        S0A += wf.x * f.y + wm.x * m.y;
        S1B += wf.y * f.z + wm.y * m.z;
        S0B += wf.y * f.w + wm.y * m.w;
    }
    // center tap: weight exactly 1
    {
        float4 c = sb[ly + 2][lx + 2];
        S1A += c.x; S0A += c.y; S1B += c.z; S0B += c.w;
    }

    int idx = b * HW + gy * W + gx;

    float a1, a0;
    a1 = expf(S1A); a0 = expf(S0A);
    float xA = fminf(fmaxf(a1 / (1e-6f + (a0 + a1)), 0.1f), 0.9f);
    a1 = expf(S1B); a0 = expf(S0B);
    float xB = fminf(fmaxf(a1 / (1e-6f + (a0 + a1)), 0.1f), 0.9f);

    if (!last) {
        __stcs(&Ld[idx], make_float4(logf(xA), logf(1.0f - xA),
                                     logf(xB), logf(1.0f - xB)));
    } else {
        // fused finalize: rgb_mask write + per-batch IoU counting
        bool t0 = (targets[idx] != 0.f);
        bool p0 = (seg[idx]  > 0.5f);
        bool p1 = (xA > 0.5f);
        bool p2 = (xB > 0.5f);
        bool p3 = (sam[idx] != 0.f);

        __stcs(&out_mask[idx], p1 ? 1.f : 0.f);

        __shared__ unsigned int c[8];
        if (tid < 8) c[tid] = 0u;
        __syncthreads();

        bool pr[4] = {p0, p1, p2, p3};
        int lane = tid & 31;
        #pragma unroll
        for (int m = 0; m < 4; m++) {
            unsigned bi = __ballot_sync(0xFFFFFFFFu, t0 && pr[m]);
            unsigned bu = __ballot_sync(0xFFFFFFFFu, t0 || pr[m]);
            if (lane == 0) {
                atomicAdd(&c[2 * m + 0], (unsigned)__popc(bi));
                atomicAdd(&c[2 * m + 1], (unsigned)__popc(bu));
            }
        }
        __syncthreads();
        if (tid < 8)
            atomicAdd(&g_cnt[b * 8 + tid], c[tid]);
    }
}

// ---------------------------------------------------------------------------
// Parallel IoU: 64 threads, one (mask m, batch b) pair each; 16-lane
// segmented shuffle reduction over batches.
// ---------------------------------------------------------------------------
__global__ void iou_kernel(float* __restrict__ out_ious) {
    int t = threadIdx.x;              // 0..63
    int m = t >> 4;                   // 0..3
    int b = t & 15;                   // 0..15
    float inter = (float)g_cnt[b * 8 + 2 * m + 0];
    float uni   = (float)g_cnt[b * 8 + 2 * m + 1];
    float v = inter / (uni + 1e-6f);
    #pragma unroll
    for (int off = 8; off > 0; off >>= 1)
        v += __shfl_down_sync(0xFFFFFFFFu, v, off, 16);
    if (b == 0)
        out_ious[m] = v * (1.0f / (float)BATCH);
}

// ---------------------------------------------------------------------------
extern "C" void kernel_launch(void* const* d_in, const int* in_sizes, int n_in,
                              void* d_out, int out_size) {
    const float* fm      = (const float*)d_in[0];  // (16,3,256,256)
    const float* seg     = (const float*)d_in[1];  // (16,256,256)
    const float* depth   = (const float*)d_in[2];
    const float* targets = (const float*)d_in[3];
    const float* sam     = (const float*)d_in[4];
    float* out = (float*)d_out;

    zero_pad<<<BATCH * NPLANE, 256>>>();
    build_kernels<<<dim3(W / BTW, H / TH, BATCH), dim3(BTW, TH)>>>(fm, depth, seg);

    // Two-phase L2-blocked schedule (8 batches x 10 iterations per phase).
    dim3 grd(W / TILEW, H / TH, GB);   // (4, 32, 8) = 1024 blocks
    for (int g = 0; g < BATCH / GB; g++) {
        int src = 0;
        for (int it = 0; it < NITER; it++) {
            mf_iter<<<grd, NT>>>(src, it == NITER - 1, g * GB,
                                 seg, targets, sam, out);
            src ^= 1;
        }
    }

    iou_kernel<<<1, 64>>>(out + (out_size - 4));
}